// round 1
// baseline (speedup 1.0000x reference)
#include <cuda_runtime.h>
#include <cstdint>

// Problem constants
#define Bn 16
#define Ln 4096
#define Cn 512
#define Tn 2048            // per-phase length
#define NTILE 63           // pooled outputs per block tile
#define MTILE 128          // co rows per block
#define NCOL 128           // GEMM columns per block (63 p0 + 1 dummy + 64 p1)
#define CI_CHUNK 16
#define WS 52              // Wsh row stride (floats), conflict-free padding
#define XSS 137            // Xs row stride (137 % 32 == 9 -> conflict-free B frags)
#define XS_S 132           // number of l-slots loaded
#define YS 130             // epilogue Y row stride
#define SMEM_BYTES (MTILE * YS * 4)   // 66560 B  (>= GEMM need 35392 B)

__device__ __forceinline__ uint32_t f2tf(float f) {
    uint32_t u;
    asm("cvt.rna.tf32.f32 %0, %1;" : "=r"(u) : "f"(f));
    return u;
}

__device__ __forceinline__ void mma_tf32(float c[4],
                                         uint32_t a0, uint32_t a1, uint32_t a2, uint32_t a3,
                                         uint32_t b0, uint32_t b1) {
    asm volatile(
        "mma.sync.aligned.m16n8k8.row.col.f32.tf32.tf32.f32 "
        "{%0,%1,%2,%3}, {%4,%5,%6,%7}, {%8,%9}, {%0,%1,%2,%3};\n"
        : "+f"(c[0]), "+f"(c[1]), "+f"(c[2]), "+f"(c[3])
        : "r"(a0), "r"(a1), "r"(a2), "r"(a3), "r"(b0), "r"(b1));
}

extern __shared__ char smem_raw[];

__global__ __launch_bounds__(256, 2)
void fused_conv_bn_elu_pool(const float* __restrict__ x,
                            const float* __restrict__ conv_w,
                            const float* __restrict__ conv_b,
                            const float* __restrict__ gamma,
                            const float* __restrict__ beta,
                            const float* __restrict__ rmean,
                            const float* __restrict__ rvar,
                            float* __restrict__ out)
{
    uint32_t* Wsh = (uint32_t*)smem_raw;                         // [128][WS]  tf32 bits
    uint32_t* Xs  = (uint32_t*)(smem_raw + MTILE * WS * 4);      // [16][XSS]  tf32 bits
    float*    Y   = (float*)smem_raw;                            // [128][YS]  epilogue (aliases)

    const int tid    = threadIdx.x;
    const int warp   = tid >> 5;
    const int lane   = tid & 31;
    const int gid    = lane >> 2;   // group id (0..7)
    const int tig    = lane & 3;    // thread in group (0..3)
    const int warp_m = warp & 1;    // 2 m-groups of 64 rows
    const int warp_n = warp >> 1;   // 4 n-groups of 32 cols

    const int j0   = blockIdx.x * NTILE;
    const int co0  = blockIdx.y * MTILE;
    const int b    = blockIdx.z;
    const int NTloc = min(NTILE, Tn - j0);

    const long xbase = (long)b * Ln * Cn;
    const int  l0    = 2 * j0 - 3;   // leftmost l needed by conv inputs

    float acc[4][4][4];
    #pragma unroll
    for (int mt = 0; mt < 4; ++mt)
        #pragma unroll
        for (int nt = 0; nt < 4; ++nt)
            #pragma unroll
            for (int i = 0; i < 4; ++i)
                acc[mt][nt][i] = 0.f;

    // =================== K loop: 32 chunks of 16 ci (x3 taps = 48 kk) ===================
    for (int ci0 = 0; ci0 < Cn; ci0 += CI_CHUNK) {
        __syncthreads();   // protect previous iteration's smem reads

        // --- load W chunk: 128 rows x 48 floats = 1536 float4 tasks (6 per thread) ---
        // K-order permutation: kk = k*16 + ci_local (tap-major) so each k8 mma step
        // has a constant conv tap k.
        #pragma unroll
        for (int it = 0; it < 6; ++it) {
            int task = tid + it * 256;          // exactly 1536 tasks
            int co   = task / 12;
            int q    = task % 12;
            const float4 v = *(const float4*)(conv_w + ((long)(co0 + co) * Cn + ci0) * 3 + q * 4);
            int pos = q * 4;
            Wsh[co * WS + ((pos + 0) % 3) * 16 + (pos + 0) / 3] = f2tf(v.x);
            Wsh[co * WS + ((pos + 1) % 3) * 16 + (pos + 1) / 3] = f2tf(v.y);
            Wsh[co * WS + ((pos + 2) % 3) * 16 + (pos + 2) / 3] = f2tf(v.z);
            Wsh[co * WS + ((pos + 3) % 3) * 16 + (pos + 3) / 3] = f2tf(v.w);
        }

        // --- load X chunk: Xs[ci_local][s] = x[b, (l0+s) mod 4096, ci0+ci_local] ---
        // 132 s-slots x 4 float4 = 528 tasks
        #pragma unroll
        for (int it = 0; it < 3; ++it) {
            int task = tid + it * 256;
            if (task < XS_S * 4) {
                int s  = task >> 2;
                int qc = task & 3;
                int l  = (l0 + s + Ln) & (Ln - 1);
                const float4 v = *(const float4*)(x + xbase + (long)l * Cn + ci0 + qc * 4);
                int cb = qc * 4;
                Xs[(cb + 0) * XSS + s] = f2tf(v.x);
                Xs[(cb + 1) * XSS + s] = f2tf(v.y);
                Xs[(cb + 2) * XSS + s] = f2tf(v.z);
                Xs[(cb + 3) * XSS + s] = f2tf(v.w);
            }
        }
        __syncthreads();

        // --- compute: 6 k8-steps over kk in [0,48) ---
        #pragma unroll
        for (int ks = 0; ks < 6; ++ks) {
            const int kk0 = ks * 8;
            const int k   = kk0 >> 4;          // conv tap (constant within step)
            uint32_t a[4][4];
            #pragma unroll
            for (int mt = 0; mt < 4; ++mt) {
                int r = warp_m * 64 + mt * 16 + gid;
                const uint32_t* wp = Wsh + r * WS + kk0 + tig;
                a[mt][0] = wp[0];
                a[mt][1] = wp[8 * WS];
                a[mt][2] = wp[4];
                a[mt][3] = wp[8 * WS + 4];
            }
            const int cib = (kk0 & 15) + tig;
            const uint32_t* xp0 = Xs + cib * XSS + 2 * k;
            uint32_t bb[4][2];
            #pragma unroll
            for (int nt = 0; nt < 4; ++nt) {
                int n = warp_n * 32 + nt * 8 + gid;
                // phase0 (n<64): s = 2n + 2k + 1 ; phase1 (n>=64): s = 2n + 2k - 128
                int s = 2 * n + ((n < 64) ? 1 : -128);
                bb[nt][0] = xp0[s];
                bb[nt][1] = xp0[4 * XSS + s];
            }
            #pragma unroll
            for (int mt = 0; mt < 4; ++mt)
                #pragma unroll
                for (int nt = 0; nt < 4; ++nt)
                    mma_tf32(acc[mt][nt], a[mt][0], a[mt][1], a[mt][2], a[mt][3],
                             bb[nt][0], bb[nt][1]);
        }
    }

    // =================== epilogue: bias + BN + ELU + residual -> Y ===================
    __syncthreads();   // all smem GEMM reads done; Y aliases Wsh/Xs
    #pragma unroll
    for (int mt = 0; mt < 4; ++mt) {
        #pragma unroll
        for (int r01 = 0; r01 < 2; ++r01) {
            const int row = warp_m * 64 + mt * 16 + gid + r01 * 8;
            const int co  = co0 + row;
            const float bias = conv_b[co];
            const float mean = rmean[co];
            const float sc   = rsqrtf(rvar[co] + 1e-5f) * gamma[co];
            const float bt   = beta[co];
            #pragma unroll
            for (int nt = 0; nt < 4; ++nt) {
                #pragma unroll
                for (int c01 = 0; c01 < 2; ++c01) {
                    const int n = warp_n * 32 + nt * 8 + 2 * tig + c01;
                    float yv = acc[mt][nt][r01 * 2 + c01] + bias;
                    float xb = (yv - mean) * sc + bt;
                    float xa = (xb > 0.f) ? xb : expm1f(xb);
                    // residual x_cl[b,co,l]: phase0 l = 2(j0+n); phase1 l = 2(j0+n)-129
                    int l = (n < 64) ? (2 * (j0 + n)) : (2 * (j0 + n) - 129);
                    l = (l + Ln) & (Ln - 1);
                    float xr = xa + x[xbase + (long)l * Cn + co];
                    Y[row * YS + n] = xr;
                }
            }
        }
    }
    __syncthreads();

    // =================== maxpool(3, stride 2, pad 1) + transpose store ===================
    for (int idx = tid; idx < MTILE * 64; idx += 256) {
        const int jj  = idx >> 7;
        const int row = idx & 127;
        if (jj < NTloc) {
            const int j = j0 + jj;
            const float NEG_INF = __int_as_float(0xff800000);
            float m0 = Y[row * YS + jj];            // xr0[j]     (l = 2j)
            float m1 = (j == 0) ? NEG_INF
                                : Y[row * YS + 64 + jj];  // xr1[j-1] (l = 2j-1)
            float m2 = Y[row * YS + 65 + jj];       // xr1[j]     (l = 2j+1)
            out[((long)b * Tn + j) * Cn + co0 + row] = fmaxf(m0, fmaxf(m1, m2));
        }
    }
}

extern "C" void kernel_launch(void* const* d_in, const int* in_sizes, int n_in,
                              void* d_out, int out_size) {
    const float* x      = (const float*)d_in[0];
    const float* conv_w = (const float*)d_in[1];
    const float* conv_b = (const float*)d_in[2];
    // d_in[3] = pad_w, d_in[4] = pad_b : unused by the reference
    const float* gamma  = (const float*)d_in[5];
    const float* beta   = (const float*)d_in[6];
    const float* rmean  = (const float*)d_in[7];
    const float* rvar   = (const float*)d_in[8];

    cudaFuncSetAttribute(fused_conv_bn_elu_pool,
                         cudaFuncAttributeMaxDynamicSharedMemorySize, SMEM_BYTES);

    dim3 grid((Tn + NTILE - 1) / NTILE, Cn / MTILE, Bn);   // 33 x 4 x 16
    fused_conv_bn_elu_pool<<<grid, 256, SMEM_BYTES>>>(
        x, conv_w, conv_b, gamma, beta, rmean, rvar, (float*)d_out);
}

// round 5
// speedup vs baseline: 1.1074x; 1.1074x over previous
#include <cuda_runtime.h>
#include <cstdint>

// ---------------- problem constants ----------------
#define Bn 16
#define Ln 4096
#define Cn 512
#define Tn 2048
#define NTILE 63           // pooled outputs per block
#define MTILE 128
#define NCHUNK 32          // 32 ci-groups of 16 (x3 taps = 48 kk each)
#define WSTR 56            // A smem row stride (words) -> conflict-free LDS.64
#define XSTR 20            // X smem row stride (words) -> conflict-free LDS.32
#define A_BYTES (MTILE * WSTR * 4)          // 28672
#define X_BYTES (66 * XSTR * 4)             // 5280 per parity array
#define XODD_OFF  A_BYTES
#define XEVEN_OFF (A_BYTES + X_BYTES)
#define STAGE_BYTES (A_BYTES + 2 * X_BYTES) // 39232
#define SMEM_BYTES (2 * STAGE_BYTES)        // 78464 (>= epilogue 66560)
#define YS 130

// Pre-transformed weights: per co row, 32 groups of 48 words.
// Within a group: pos = (kk>>3)*8 + 2*((kk&7)&3) + ((kk&7)>>2), kk = k*16 + ci_local.
__device__ uint32_t g_Wt2[Cn * Cn * 3];

__device__ __forceinline__ uint32_t f2tf(float f) {
    uint32_t u; asm("cvt.rna.tf32.f32 %0, %1;" : "=r"(u) : "f"(f)); return u;
}
__device__ __forceinline__ uint32_t smem_u32(const void* p) {
    uint32_t a;
    asm("{ .reg .u64 t; cvta.to.shared.u64 t, %1; cvt.u32.u64 %0, t; }" : "=r"(a) : "l"(p));
    return a;
}
__device__ __forceinline__ void cpa16(uint32_t dst, const void* src) {
    asm volatile("cp.async.cg.shared.global [%0], [%1], 16;" :: "r"(dst), "l"(src));
}
__device__ __forceinline__ void mma_tf32(float c[4],
                                         uint32_t a0, uint32_t a1, uint32_t a2, uint32_t a3,
                                         uint32_t b0, uint32_t b1) {
    asm volatile(
        "mma.sync.aligned.m16n8k8.row.col.f32.tf32.tf32.f32 "
        "{%0,%1,%2,%3}, {%4,%5,%6,%7}, {%8,%9}, {%0,%1,%2,%3};\n"
        : "+f"(c[0]), "+f"(c[1]), "+f"(c[2]), "+f"(c[3])
        : "r"(a0), "r"(a1), "r"(a2), "r"(a3), "r"(b0), "r"(b1));
}

// ---------------- prepass: conv_w -> permuted tf32 weights ----------------
__global__ void prep_w_kernel(const float* __restrict__ conv_w) {
    int idx = blockIdx.x * 256 + threadIdx.x;
    if (idx >= Cn * Cn * 3) return;
    int co = idx / 1536;
    int r  = idx - co * 1536;
    int cg = r / 48;
    int p  = r - cg * 48;
    int grp = p >> 3, pl = p & 7;
    int kkl = (pl >> 1) + ((pl & 1) << 2);   // inverse of in-group permute
    int kk  = grp * 8 + kkl;
    int k   = kk >> 4, cil = kk & 15;
    g_Wt2[idx] = f2tf(conv_w[(co * Cn + cg * 16 + cil) * 3 + k]);
}

// ---------------- main fused kernel ----------------
extern __shared__ __align__(16) char smem_raw[];

__global__ __launch_bounds__(256, 2)
void fused_conv_bn_elu_pool(const float* __restrict__ x,
                            const float* __restrict__ conv_b,
                            const float* __restrict__ gamma,
                            const float* __restrict__ beta,
                            const float* __restrict__ rmean,
                            const float* __restrict__ rvar,
                            float* __restrict__ out)
{
    const uint32_t sbase = smem_u32(smem_raw);
    const int tid    = threadIdx.x;
    const int warp   = tid >> 5;
    const int lane   = tid & 31;
    const int gid    = lane >> 2;   // 0..7
    const int tig    = lane & 3;    // 0..3
    const int warp_m = warp & 1;    // 2 m-groups of 64 rows
    const int warp_n = warp >> 1;   // 4 n-groups of 32 cols

    const int j0   = blockIdx.x * NTILE;
    const int co0  = blockIdx.y * MTILE;
    const int b    = blockIdx.z;
    const int NTloc = min(NTILE, Tn - j0);
    const long xbase = (long)b * Ln * Cn;
    const int  l0    = 2 * j0 - 3;

    float acc[4][4][4];
    #pragma unroll
    for (int mt = 0; mt < 4; ++mt)
        #pragma unroll
        for (int nt = 0; nt < 4; ++nt)
            #pragma unroll
            for (int i = 0; i < 4; ++i) acc[mt][nt][i] = 0.f;

    // ---- async producer: chunk c -> stage c&1 ----
    auto produce = [&](int c) {
        const int s = c & 1;
        const uint32_t stb = sbase + s * STAGE_BYTES;
        const uint32_t* wsrc = g_Wt2 + (long)co0 * 1536 + c * 48;
        #pragma unroll
        for (int q = 0; q < 6; ++q) {                 // A: 1536 16B pieces
            int task = tid + q * 256;
            int co = task / 12, qq = task - co * 12;
            cpa16(stb + co * (WSTR * 4) + qq * 16, wsrc + (long)co * 1536 + qq * 4);
        }
        const int ci0 = c * 16;
        #pragma unroll
        for (int q = 0; q < 3; ++q) {                 // X: 528 16B pieces
            int task = tid + q * 256;
            if (task < 528) {
                int slot = task >> 2, qc = task & 3;
                int l = (l0 + slot + Ln) & (Ln - 1);
                uint32_t dst = stb + ((slot & 1) ? XODD_OFF : XEVEN_OFF)
                             + (slot >> 1) * (XSTR * 4) + qc * 16;
                cpa16(dst, x + xbase + (long)l * Cn + ci0 + qc * 4);
            }
        }
        asm volatile("cp.async.commit_group;" ::: "memory");
    };

    produce(0);
    produce(1);

    const int nwadj = warp_n * 32 + gid - ((warp_n >= 2) ? 64 : 0);

    for (int i = 0; i < NCHUNK; ++i) {
        if (i == NCHUNK - 1) asm volatile("cp.async.wait_group 0;" ::: "memory");
        else                 asm volatile("cp.async.wait_group 1;" ::: "memory");
        __syncthreads();

        const char* stp = smem_raw + (i & 1) * STAGE_BYTES;
        const uint32_t* W  = (const uint32_t*)stp;
        const float*    Xb = (const float*)(stp + ((warp_n >= 2) ? XEVEN_OFF : XODD_OFF));

        #pragma unroll
        for (int ks = 0; ks < 6; ++ks) {
            const int kk0 = ks * 8;
            const int k   = ks >> 1;
            const int cib = ((ks & 1) << 3) + tig;

            uint32_t a[4][4];
            #pragma unroll
            for (int mt = 0; mt < 4; ++mt) {
                const uint32_t* wp = W + (warp_m * 64 + mt * 16 + gid) * WSTR + kk0 + 2 * tig;
                uint2 lo = *(const uint2*)wp;
                uint2 hi = *(const uint2*)(wp + 8 * WSTR);
                a[mt][0] = lo.x; a[mt][2] = lo.y;
                a[mt][1] = hi.x; a[mt][3] = hi.y;
            }

            uint32_t bb[4][2];
            const float* xrow = Xb + (nwadj + k) * XSTR + cib;
            #pragma unroll
            for (int nt = 0; nt < 4; ++nt) {
                bb[nt][0] = f2tf(xrow[nt * 8 * XSTR]);
                bb[nt][1] = f2tf(xrow[nt * 8 * XSTR + 4]);
            }

            #pragma unroll
            for (int mt = 0; mt < 4; ++mt)
                #pragma unroll
                for (int nt = 0; nt < 4; ++nt)
                    mma_tf32(acc[mt][nt], a[mt][0], a[mt][1], a[mt][2], a[mt][3],
                             bb[nt][0], bb[nt][1]);
        }
        __syncthreads();
        if (i + 2 < NCHUNK) produce(i + 2);
    }

    // ---- epilogue: bias + BN + ELU + residual -> Y (aliases stage smem) ----
    float* Y = (float*)smem_raw;
    #pragma unroll
    for (int mt = 0; mt < 4; ++mt) {
        #pragma unroll
        for (int r01 = 0; r01 < 2; ++r01) {
            const int row = warp_m * 64 + mt * 16 + gid + r01 * 8;
            const int co  = co0 + row;
            const float bias = conv_b[co];
            const float mean = rmean[co];
            const float sc   = rsqrtf(rvar[co] + 1e-5f) * gamma[co];
            const float bt   = beta[co];
            #pragma unroll
            for (int nt = 0; nt < 4; ++nt) {
                #pragma unroll
                for (int c01 = 0; c01 < 2; ++c01) {
                    const int n = warp_n * 32 + nt * 8 + 2 * tig + c01;
                    float yv = acc[mt][nt][r01 * 2 + c01] + bias;
                    float xb = (yv - mean) * sc + bt;
                    float xa = (xb > 0.f) ? xb : expm1f(xb);
                    int l = (n < 64) ? (2 * (j0 + n)) : (2 * (j0 + n) - 129);
                    l = (l + Ln) & (Ln - 1);
                    Y[row * YS + n] = xa + x[xbase + (long)l * Cn + co];
                }
            }
        }
    }
    __syncthreads();

    // ---- maxpool(3, stride 2, pad 1) + transposed store ----
    for (int idx = tid; idx < MTILE * 64; idx += 256) {
        const int jj  = idx >> 7;
        const int row = idx & 127;
        if (jj < NTloc) {
            const int j = j0 + jj;
            const float NEG_INF = __int_as_float(0xff800000);
            float m0 = Y[row * YS + jj];                    // p0, t=j   (l=2j)
            float m1 = (j == 0) ? NEG_INF
                                : Y[row * YS + 64 + jj];    // p1, t=j-1 (l=2j-1)
            float m2 = Y[row * YS + 65 + jj];               // p1, t=j   (l=2j+1)
            out[((long)b * Tn + j) * Cn + co0 + row] = fmaxf(m0, fmaxf(m1, m2));
        }
    }
}

extern "C" void kernel_launch(void* const* d_in, const int* in_sizes, int n_in,
                              void* d_out, int out_size) {
    const float* x      = (const float*)d_in[0];
    const float* conv_w = (const float*)d_in[1];
    const float* conv_b = (const float*)d_in[2];
    // d_in[3]=pad_w, d_in[4]=pad_b unused by reference
    const float* gamma  = (const float*)d_in[5];
    const float* beta   = (const float*)d_in[6];
    const float* rmean  = (const float*)d_in[7];
    const float* rvar   = (const float*)d_in[8];

    prep_w_kernel<<<(Cn * Cn * 3 + 255) / 256, 256>>>(conv_w);

    cudaFuncSetAttribute(fused_conv_bn_elu_pool,
                         cudaFuncAttributeMaxDynamicSharedMemorySize, SMEM_BYTES);
    dim3 grid((Tn + NTILE - 1) / NTILE, Cn / MTILE, Bn);   // 33 x 4 x 16
    fused_conv_bn_elu_pool<<<grid, 256, SMEM_BYTES>>>(
        x, conv_b, gamma, beta, rmean, rvar, (float*)d_out);
}